// round 6
// baseline (speedup 1.0000x reference)
#include <cuda_runtime.h>
#include <cstdint>

#define NG    1024
#define DIM   128
#define HID   512
#define MAXE  500000
#define HB    148          // edge-partition blocks for hist/scatter (must match)

// ---- scratch (no allocations allowed) ----
__device__ float    d_edge_mean[NG * DIM];
__device__ float    d_node_mean[NG * DIM];
__device__ int      d_node_start[NG + 1];
__device__ unsigned d_gcnt[NG];
__device__ unsigned d_goff[NG];
__device__ unsigned d_h[HB * NG];       // per-block histograms
__device__ unsigned d_hoff[HB * NG];    // per-(block,graph) exclusive prefix
__device__ int      d_eg[MAXE];         // graph id per edge
__device__ int      d_bucket[MAXE];     // edge ids grouped by graph
__device__ volatile int d_flag;         // scan-done flag (reset by K1)

// ---------------------------------------------------------------------------
__device__ __forceinline__ int load_idx(const void* p, long long i, int idx64) {
    return idx64 ? (int)((const long long*)p)[i] : ((const int*)p)[i];
}
// dtype probe on edge_index: node ids are random nonzero ints, so
// all-zero odd 32-bit words <=> int64 storage.
__device__ __forceinline__ int probe_idx64(const void* edge_index) {
    const int* w = (const int*)edge_index;
    int all_zero = 1;
    #pragma unroll
    for (int i = 1; i < 128; i += 2) all_zero &= (w[i] == 0);
    return all_zero;
}

// ---------------------------------------------------------------------------
// K1: blocks 0..147 -> edge histogram + d_eg (direct batch gather)
//     blocks 148..149 -> node_start boundaries
//     block 150 -> reset flag
// ---------------------------------------------------------------------------
__global__ void __launch_bounds__(1024) prep_kernel(
        const void* __restrict__ edge_index,
        const void* __restrict__ batch,
        int n_edges, int n_nodes) {
    int b = blockIdx.x, tid = threadIdx.x;

    if (b < HB) {
        __shared__ unsigned s_cnt[NG];
        __shared__ int s_idx64;
        if (tid == 0) s_idx64 = probe_idx64(edge_index);
        if (tid < NG) s_cnt[tid] = 0u;
        __syncthreads();
        int idx64 = s_idx64;

        int epb = (n_edges + HB - 1) / HB;
        int e0 = b * epb, e1 = e0 + epb; if (e1 > n_edges) e1 = n_edges;

        for (int e = e0 + tid; e < e1; e += 1024) {
            int src = load_idx(edge_index, e, idx64);   // row 0 of edge_index
            int g   = load_idx(batch, src, idx64);      // batch is L2-resident
            d_eg[e] = g;
            atomicAdd(&s_cnt[g], 1u);
        }
        __syncthreads();
        if (tid < NG) d_h[b * NG + tid] = s_cnt[tid];
    } else if (b < 150) {
        int g = (b - HB) * 1024 + tid;
        if (g <= NG) {
            int idx64 = probe_idx64(edge_index);
            int lo = 0, hi = n_nodes;
            while (lo < hi) {
                int m = (lo + hi) >> 1;
                if (load_idx(batch, m, idx64) < g) lo = m + 1; else hi = m;
            }
            d_node_start[g] = lo;
        }
    } else {
        if (tid == 0) d_flag = 0;
    }
}

// ---------------------------------------------------------------------------
// K2: block 0        -> scans (column prefix + bucket offsets), then flag=1
//     blocks 1..1024 -> node mean (contiguous rows, no atomics)
//     blocks 1025+   -> scatter (spin on flag first)
// ---------------------------------------------------------------------------
__global__ void __launch_bounds__(256) mid_kernel(
        const float* __restrict__ x, int n_edges) {
    __shared__ unsigned s_a[NG];
    __shared__ unsigned s_b[NG];
    __shared__ unsigned s_w[256];
    __shared__ float4   s_red[8][32];

    int b = blockIdx.x, tid = threadIdx.x;

    if (b == 0) {
        // phase A: per-graph column scan over the HB block histograms
        #pragma unroll
        for (int c = 0; c < 4; c++) {
            int g = tid + c * 256;
            unsigned run = 0;
            #pragma unroll 4
            for (int bb = 0; bb < HB; bb++) {
                unsigned v = d_h[bb * NG + g];
                d_hoff[bb * NG + g] = run;
                run += v;
            }
            s_a[g] = run;
            d_gcnt[g] = run;
        }
        __syncthreads();
        // phase B: exclusive scan of the 1024 totals
        unsigned a0 = s_a[tid * 4], a1 = s_a[tid * 4 + 1],
                 a2 = s_a[tid * 4 + 2], a3 = s_a[tid * 4 + 3];
        unsigned ts = a0 + a1 + a2 + a3;
        s_w[tid] = ts;
        __syncthreads();
        for (int off = 1; off < 256; off <<= 1) {
            unsigned add = (tid >= off) ? s_w[tid - off] : 0u;
            __syncthreads();
            s_w[tid] += add;
            __syncthreads();
        }
        unsigned base = s_w[tid] - ts;
        d_goff[tid * 4]     = base;
        d_goff[tid * 4 + 1] = base + a0;
        d_goff[tid * 4 + 2] = base + a0 + a1;
        d_goff[tid * 4 + 3] = base + a0 + a1 + a2;
        __threadfence();
        __syncthreads();
        if (tid == 0) d_flag = 1;
    } else if (b <= NG) {
        // ---- node mean: graph g's rows are contiguous in x ----
        int g = b - 1;
        int s = d_node_start[g], e = d_node_start[g + 1];
        int cnt = e - s;
        int lane = tid & 31, w = tid >> 5;

        const float4* xr = (const float4*)x;
        float4 acc = make_float4(0.f, 0.f, 0.f, 0.f);
        for (int n = s + w; n < e; n += 8) {
            float4 v = xr[(size_t)n * 32 + lane];
            acc.x += v.x; acc.y += v.y; acc.z += v.z; acc.w += v.w;
        }
        s_red[w][lane] = acc;
        __syncthreads();
        if (w == 0) {
            float4 t = s_red[0][lane];
            #pragma unroll
            for (int i = 1; i < 8; i++) {
                float4 q = s_red[i][lane];
                t.x += q.x; t.y += q.y; t.z += q.z; t.w += q.w;
            }
            float inv = 1.0f / (float)(cnt > 0 ? cnt : 1);
            t.x *= inv; t.y *= inv; t.z *= inv; t.w *= inv;
            ((float4*)(d_node_mean + (size_t)g * DIM))[lane] = t;
        }
    } else {
        // ---- scatter: wait for scan, then bucket the edge ids ----
        int sb = b - (NG + 1);
        if (tid == 0) {
            while (d_flag == 0) __nanosleep(64);
            __threadfence();
        }
        __syncthreads();

        for (int i = tid; i < NG; i += 256) {
            s_a[i] = d_goff[i] + d_hoff[sb * NG + i];   // base
            s_b[i] = 0u;                                // rank counter
        }
        __syncthreads();

        int epb = (n_edges + HB - 1) / HB;
        int e0 = sb * epb, e1 = e0 + epb; if (e1 > n_edges) e1 = n_edges;
        for (int e = e0 + tid; e < e1; e += 256) {
            int g = d_eg[e];
            unsigned pos = s_a[g] + atomicAdd(&s_b[g], 1u);
            d_bucket[pos] = e;
        }
    }
}

// ---------------------------------------------------------------------------
// K3: atomic-free edge mean. Block per graph, 16 warps, 2 rows in flight.
// ---------------------------------------------------------------------------
__global__ void __launch_bounds__(512) esum_kernel(const float* __restrict__ edge_attr) {
    int g    = blockIdx.x;
    int lane = threadIdx.x & 31;
    int w    = threadIdx.x >> 5;

    int s = (int)d_goff[g];
    int n = (int)d_gcnt[g];

    const float4* ea = (const float4*)edge_attr;
    float4 a0 = make_float4(0.f, 0.f, 0.f, 0.f);
    float4 a1 = make_float4(0.f, 0.f, 0.f, 0.f);

    int j  = w * 2;
    int c0 = (j     < n) ? d_bucket[s + j]     : -1;
    int c1 = (j + 1 < n) ? d_bucket[s + j + 1] : -1;
    for (; j < n; j += 32) {
        int f0 = (j + 32 < n) ? d_bucket[s + j + 32] : -1;
        int f1 = (j + 33 < n) ? d_bucket[s + j + 33] : -1;
        if (c0 >= 0) {
            float4 v = ea[(size_t)c0 * 32 + lane];
            a0.x += v.x; a0.y += v.y; a0.z += v.z; a0.w += v.w;
        }
        if (c1 >= 0) {
            float4 v = ea[(size_t)c1 * 32 + lane];
            a1.x += v.x; a1.y += v.y; a1.z += v.z; a1.w += v.w;
        }
        c0 = f0; c1 = f1;
    }
    a0.x += a1.x; a0.y += a1.y; a0.z += a1.z; a0.w += a1.w;

    __shared__ float4 sacc[16][32];
    sacc[w][lane] = a0;
    __syncthreads();
    if (w == 0) {
        float4 t = sacc[0][lane];
        #pragma unroll
        for (int i = 1; i < 16; i++) {
            float4 q = sacc[i][lane];
            t.x += q.x; t.y += q.y; t.z += q.z; t.w += q.w;
        }
        float inv = 1.0f / (float)(n > 0 ? n : 1);
        t.x *= inv; t.y *= inv; t.z *= inv; t.w *= inv;
        ((float4*)(d_edge_mean + (size_t)g * DIM))[lane] = t;
    }
}

// ---------------------------------------------------------------------------
// K4: MLP + residual + LayerNorm. 128 blocks x 8 graphs, 256 threads.
// ---------------------------------------------------------------------------
__global__ void __launch_bounds__(256) mlp_kernel(
        const float* __restrict__ u,
        const float* __restrict__ W1, const float* __restrict__ b1,
        const float* __restrict__ W2, const float* __restrict__ b2,
        const float* __restrict__ gamma, const float* __restrict__ beta,
        float* __restrict__ out) {
    __shared__ float inp[8][3 * DIM];
    __shared__ float hbuf[8][HID];
    __shared__ float ysm[8][DIM];

    int tid = threadIdx.x;
    int g0  = blockIdx.x * 8;

    for (int idx = tid; idx < 8 * DIM; idx += 256) {
        int g = idx >> 7, d = idx & (DIM - 1);
        int gg = g0 + g;
        inp[g][d]           = u[(size_t)gg * DIM + d];
        inp[g][DIM + d]     = d_edge_mean[(size_t)gg * DIM + d];
        inp[g][2 * DIM + d] = d_node_mean[(size_t)gg * DIM + d];
    }
    __syncthreads();

    // layer 1: h = relu(inp @ W1 + b1)
    {
        float acc0[8], acc1[8];
        float bb0 = b1[tid], bb1 = b1[tid + 256];
        #pragma unroll
        for (int g = 0; g < 8; g++) { acc0[g] = bb0; acc1[g] = bb1; }

        for (int k = 0; k < 3 * DIM; k += 4) {
            float4 iv[8];
            #pragma unroll
            for (int g = 0; g < 8; g++) iv[g] = *(const float4*)&inp[g][k];
            #pragma unroll
            for (int kk = 0; kk < 4; kk++) {
                float w0 = W1[(size_t)(k + kk) * HID + tid];
                float w1 = W1[(size_t)(k + kk) * HID + tid + 256];
                #pragma unroll
                for (int g = 0; g < 8; g++) {
                    float xv = (kk == 0) ? iv[g].x : (kk == 1) ? iv[g].y
                             : (kk == 2) ? iv[g].z : iv[g].w;
                    acc0[g] = fmaf(xv, w0, acc0[g]);
                    acc1[g] = fmaf(xv, w1, acc1[g]);
                }
            }
        }
        #pragma unroll
        for (int g = 0; g < 8; g++) {
            hbuf[g][tid]       = fmaxf(acc0[g], 0.f);
            hbuf[g][tid + 256] = fmaxf(acc1[g], 0.f);
        }
    }
    __syncthreads();

    // layer 2
    {
        int g  = tid >> 5;
        int d0 = (tid & 31) * 4;
        float4 acc = *(const float4*)&b2[d0];
        for (int k = 0; k < HID; k++) {
            float hv = hbuf[g][k];
            float4 w = *(const float4*)&W2[(size_t)k * DIM + d0];
            acc.x = fmaf(hv, w.x, acc.x);
            acc.y = fmaf(hv, w.y, acc.y);
            acc.z = fmaf(hv, w.z, acc.z);
            acc.w = fmaf(hv, w.w, acc.w);
        }
        *(float4*)&ysm[g][d0] = acc;
    }
    __syncthreads();

    // residual + layernorm
    {
        int w = tid >> 5, lane = tid & 31;
        int gg = g0 + w;
        float4 v  = *(const float4*)&ysm[w][lane * 4];
        float4 uu = *(const float4*)&u[(size_t)gg * DIM + lane * 4];
        v.x += uu.x; v.y += uu.y; v.z += uu.z; v.w += uu.w;

        float sm = v.x + v.y + v.z + v.w;
        #pragma unroll
        for (int off = 16; off; off >>= 1) sm += __shfl_xor_sync(0xffffffffu, sm, off);
        float mu = sm * (1.0f / DIM);

        float dx = v.x - mu, dy = v.y - mu, dz = v.z - mu, dw = v.w - mu;
        float sq = dx * dx + dy * dy + dz * dz + dw * dw;
        #pragma unroll
        for (int off = 16; off; off >>= 1) sq += __shfl_xor_sync(0xffffffffu, sq, off);
        float rs = rsqrtf(sq * (1.0f / DIM) + 1e-5f);

        float4 gm = *(const float4*)&gamma[lane * 4];
        float4 bt = *(const float4*)&beta[lane * 4];
        float4 o;
        o.x = dx * rs * gm.x + bt.x;
        o.y = dy * rs * gm.y + bt.y;
        o.z = dz * rs * gm.z + bt.z;
        o.w = dw * rs * gm.w + bt.w;
        *(float4*)&out[(size_t)gg * DIM + lane * 4] = o;
    }
}

// ---------------------------------------------------------------------------
extern "C" void kernel_launch(void* const* d_in, const int* in_sizes, int n_in,
                              void* d_out, int out_size) {
    const float* x         = (const float*)d_in[0];
    const float* edge_attr = (const float*)d_in[1];
    const float* u         = (const float*)d_in[2];
    const float* W1        = (const float*)d_in[3];
    const float* b1        = (const float*)d_in[4];
    const float* W2        = (const float*)d_in[5];
    const float* b2        = (const float*)d_in[6];
    const float* gamma     = (const float*)d_in[7];
    const float* beta      = (const float*)d_in[8];
    const void* edge_index = d_in[9];
    const void* batch      = d_in[10];

    int n_edges = in_sizes[9] / 2;
    int n_nodes = in_sizes[10];
    float* out = (float*)d_out;

    prep_kernel<<<151, 1024>>>(edge_index, batch, n_edges, n_nodes);       // 1
    mid_kernel<<<1 + NG + HB, 256>>>(x, n_edges);                          // 2
    esum_kernel<<<NG, 512>>>(edge_attr);                                   // 3
    mlp_kernel<<<NG / 8, 256>>>(u, W1, b1, W2, b2, gamma, beta, out);      // 4
}

// round 8
// speedup vs baseline: 1.4034x; 1.4034x over previous
#include <cuda_runtime.h>
#include <cstdint>

// NOTE R8: identical to R7 submission — R7 hit a broker/container infra
// failure ("GB300 container failed twice") and never ran. Resubmitting to
// get the clean measurement for the 3-launch design.

#define NG    1024
#define DIM   128
#define HID   512
#define NREP  16
#define EB    1184     // edge blocks in fused kernel

// ---- scratch (no allocations allowed) ----
__device__ float    d_escratch[NREP * NG * DIM];   // 8 MB replicated edge sums
__device__ unsigned d_ecnt[NREP * NG];             // replicated edge counts
__device__ float    d_node_mean[NG * DIM];
__device__ int      d_node_start[NG + 1];

// ---------------------------------------------------------------------------
__device__ __forceinline__ int load_idx(const void* p, long long i, int idx64) {
    return idx64 ? (int)((const long long*)p)[i] : ((const int*)p)[i];
}
// dtype probe on edge_index: node ids are random nonzero ints, so
// all-zero odd 32-bit words <=> int64 storage.
__device__ __forceinline__ int probe_idx64(const void* edge_index) {
    const int* w = (const int*)edge_index;
    int all_zero = 1;
    #pragma unroll
    for (int i = 1; i < 128; i += 2) all_zero &= (w[i] == 0);
    return all_zero;
}

// ---------------------------------------------------------------------------
// K1: zero edge scratch + counts; spare blocks compute node_start boundaries.
// ---------------------------------------------------------------------------
__global__ void __launch_bounds__(256) zero_kernel(
        const void* __restrict__ batch,
        const void* __restrict__ edge_index,
        int n_nodes) {
    int b = blockIdx.x, tid = threadIdx.x;
    if (b < 2048) {
        int i = b * 256 + tid;                      // 524288 float4 = 8 MB
        ((float4*)d_escratch)[i] = make_float4(0.f, 0.f, 0.f, 0.f);
        if (i < NREP * NG) d_ecnt[i] = 0u;
    } else {
        int g = (b - 2048) * 256 + tid;             // 5 blocks cover 1025
        if (g <= NG) {
            int idx64 = probe_idx64(edge_index);
            int lo = 0, hi = n_nodes;
            while (lo < hi) {
                int m = (lo + hi) >> 1;
                if (load_idx(batch, m, idx64) < g) lo = m + 1; else hi = m;
            }
            d_node_start[g] = lo;
        }
    }
}

// ---------------------------------------------------------------------------
// K2: blocks 0..EB-1  -> edge scatter-accumulate (warp per edge row, red.v4)
//     blocks EB..     -> node mean (block per graph, contiguous rows)
// ---------------------------------------------------------------------------
__global__ void __launch_bounds__(256) edgenode_kernel(
        const float* __restrict__ edge_attr,
        const float* __restrict__ x,
        const void* __restrict__ edge_index,
        const void* __restrict__ batch,
        int n_edges) {
    int b = blockIdx.x, tid = threadIdx.x;
    int lane = tid & 31;

    if (b < EB) {
        __shared__ int s_idx64;
        if (tid == 0) s_idx64 = probe_idx64(edge_index);
        __syncthreads();
        int idx64 = s_idx64;

        int warp_g = (b * 256 + tid) >> 5;
        int nwarps = (EB * 256) >> 5;
        int rep    = warp_g & (NREP - 1);

        for (int e = warp_g; e < n_edges; e += nwarps) {
            int g = 0;
            if (lane == 0) {
                int src = load_idx(edge_index, e, idx64);   // row 0 of edge_index
                g = load_idx(batch, src, idx64);            // batch L2-resident
            }
            g = __shfl_sync(0xffffffffu, g, 0);

            float4 v = ((const float4*)(edge_attr + (size_t)e * DIM))[lane];
            float* dst = d_escratch + ((size_t)rep * NG + g) * DIM + lane * 4;
            asm volatile("red.global.add.v4.f32 [%0], {%1,%2,%3,%4};"
                         :: "l"(dst), "f"(v.x), "f"(v.y), "f"(v.z), "f"(v.w)
                         : "memory");
            if (lane == 0) atomicAdd(&d_ecnt[rep * NG + g], 1u);
        }
    } else {
        // node mean: graph g's rows are contiguous in x (batch is sorted)
        int g = b - EB;
        int s = d_node_start[g], e = d_node_start[g + 1];
        int cnt = e - s;
        int w = tid >> 5;

        const float4* xr = (const float4*)x;
        float4 acc = make_float4(0.f, 0.f, 0.f, 0.f);
        for (int n = s + w; n < e; n += 8) {
            float4 v = xr[(size_t)n * 32 + lane];
            acc.x += v.x; acc.y += v.y; acc.z += v.z; acc.w += v.w;
        }
        __shared__ float4 s_red[8][32];
        s_red[w][lane] = acc;
        __syncthreads();
        if (w == 0) {
            float4 t = s_red[0][lane];
            #pragma unroll
            for (int i = 1; i < 8; i++) {
                float4 q = s_red[i][lane];
                t.x += q.x; t.y += q.y; t.z += q.z; t.w += q.w;
            }
            float inv = 1.0f / (float)(cnt > 0 ? cnt : 1);
            t.x *= inv; t.y *= inv; t.z *= inv; t.w *= inv;
            ((float4*)(d_node_mean + (size_t)g * DIM))[lane] = t;
        }
    }
}

// ---------------------------------------------------------------------------
// K3: replica-reduce + MLP + residual + LayerNorm.
// 128 blocks x 8 graphs, 512 threads (16 warps), deep load pipelining.
// ---------------------------------------------------------------------------
__global__ void __launch_bounds__(512) mlp_kernel(
        const float* __restrict__ u,
        const float* __restrict__ W1, const float* __restrict__ b1,
        const float* __restrict__ W2, const float* __restrict__ b2,
        const float* __restrict__ gamma, const float* __restrict__ beta,
        float* __restrict__ out) {
    __shared__ float inp[8][3 * DIM];
    __shared__ float hbuf[8][HID];
    __shared__ float ysm[8][DIM];
    __shared__ float s_ecnt[8];

    int tid = threadIdx.x;
    int g0  = blockIdx.x * 8;

    if (tid < 8) {
        unsigned c = 0;
        #pragma unroll
        for (int r = 0; r < NREP; r++) c += d_ecnt[r * NG + g0 + tid];
        s_ecnt[tid] = 1.0f / (float)(c > 0u ? c : 1u);
    }
    __syncthreads();

    // build input rows: [u | edge_mean | node_mean]
    for (int idx = tid; idx < 8 * DIM; idx += 512) {
        int g = idx >> 7, d = idx & (DIM - 1);
        int gg = g0 + g;
        float es = 0.f;
        #pragma unroll
        for (int r = 0; r < NREP; r++)
            es += d_escratch[((size_t)r * NG + gg) * DIM + d];
        inp[g][d]           = u[(size_t)gg * DIM + d];
        inp[g][DIM + d]     = es * s_ecnt[g];
        inp[g][2 * DIM + d] = d_node_mean[(size_t)gg * DIM + d];
    }
    __syncthreads();

    // ---- layer 1: thread owns hidden col tid; 8-deep weight prefetch ----
    {
        float acc[8];
        float bb = b1[tid];
        #pragma unroll
        for (int g = 0; g < 8; g++) acc[g] = bb;

        float wcur[8], wnxt[8];
        #pragma unroll
        for (int kk = 0; kk < 8; kk++) wcur[kk] = W1[(size_t)kk * HID + tid];

        for (int k = 0; k < 3 * DIM; k += 8) {
            if (k + 8 < 3 * DIM) {
                #pragma unroll
                for (int kk = 0; kk < 8; kk++)
                    wnxt[kk] = W1[(size_t)(k + 8 + kk) * HID + tid];
            }
            #pragma unroll
            for (int kk = 0; kk < 8; kk++) {
                float wv = wcur[kk];
                #pragma unroll
                for (int g = 0; g < 8; g++)
                    acc[g] = fmaf(inp[g][k + kk], wv, acc[g]);
            }
            #pragma unroll
            for (int kk = 0; kk < 8; kk++) wcur[kk] = wnxt[kk];
        }
        #pragma unroll
        for (int g = 0; g < 8; g++)
            hbuf[g][tid] = fmaxf(acc[g], 0.f);
    }
    __syncthreads();

    // ---- layer 2: thread owns (graph tid>>6, float2 cols); pipelined ----
    {
        int g  = tid >> 6;            // 8 graphs x 64 threads
        int c0 = (tid & 63) * 2;      // 2 output cols per thread
        float2 acc = *(const float2*)&b2[c0];

        float2 wcur[8], wnxt[8];
        #pragma unroll
        for (int kk = 0; kk < 8; kk++)
            wcur[kk] = *(const float2*)&W2[(size_t)kk * DIM + c0];

        for (int k = 0; k < HID; k += 8) {
            if (k + 8 < HID) {
                #pragma unroll
                for (int kk = 0; kk < 8; kk++)
                    wnxt[kk] = *(const float2*)&W2[(size_t)(k + 8 + kk) * DIM + c0];
            }
            #pragma unroll
            for (int kk = 0; kk < 8; kk++) {
                float hv = hbuf[g][k + kk];
                acc.x = fmaf(hv, wcur[kk].x, acc.x);
                acc.y = fmaf(hv, wcur[kk].y, acc.y);
            }
            #pragma unroll
            for (int kk = 0; kk < 8; kk++) wcur[kk] = wnxt[kk];
        }
        *(float2*)&ysm[g][c0] = acc;
    }
    __syncthreads();

    // ---- residual + layernorm: warps 0..7, one graph each ----
    {
        int w = tid >> 5, lane = tid & 31;
        if (w < 8) {
            int gg = g0 + w;
            float4 v  = *(const float4*)&ysm[w][lane * 4];
            float4 uu = *(const float4*)&u[(size_t)gg * DIM + lane * 4];
            v.x += uu.x; v.y += uu.y; v.z += uu.z; v.w += uu.w;

            float sm = v.x + v.y + v.z + v.w;
            #pragma unroll
            for (int off = 16; off; off >>= 1) sm += __shfl_xor_sync(0xffffffffu, sm, off);
            float mu = sm * (1.0f / DIM);

            float dx = v.x - mu, dy = v.y - mu, dz = v.z - mu, dw = v.w - mu;
            float sq = dx * dx + dy * dy + dz * dz + dw * dw;
            #pragma unroll
            for (int off = 16; off; off >>= 1) sq += __shfl_xor_sync(0xffffffffu, sq, off);
            float rs = rsqrtf(sq * (1.0f / DIM) + 1e-5f);

            float4 gm = *(const float4*)&gamma[lane * 4];
            float4 bt = *(const float4*)&beta[lane * 4];
            float4 o;
            o.x = dx * rs * gm.x + bt.x;
            o.y = dy * rs * gm.y + bt.y;
            o.z = dz * rs * gm.z + bt.z;
            o.w = dw * rs * gm.w + bt.w;
            *(float4*)&out[(size_t)gg * DIM + lane * 4] = o;
        }
    }
}

// ---------------------------------------------------------------------------
extern "C" void kernel_launch(void* const* d_in, const int* in_sizes, int n_in,
                              void* d_out, int out_size) {
    const float* x         = (const float*)d_in[0];
    const float* edge_attr = (const float*)d_in[1];
    const float* u         = (const float*)d_in[2];
    const float* W1        = (const float*)d_in[3];
    const float* b1        = (const float*)d_in[4];
    const float* W2        = (const float*)d_in[5];
    const float* b2        = (const float*)d_in[6];
    const float* gamma     = (const float*)d_in[7];
    const float* beta      = (const float*)d_in[8];
    const void* edge_index = d_in[9];
    const void* batch      = d_in[10];

    int n_edges = in_sizes[9] / 2;
    int n_nodes = in_sizes[10];
    float* out = (float*)d_out;

    zero_kernel<<<2053, 256>>>(batch, edge_index, n_nodes);                        // 1
    edgenode_kernel<<<EB + NG, 256>>>(edge_attr, x, edge_index, batch, n_edges);   // 2
    mlp_kernel<<<NG / 8, 512>>>(u, W1, b1, W2, b2, gamma, beta, out);              // 3
}

// round 9
// speedup vs baseline: 1.4239x; 1.0146x over previous
#include <cuda_runtime.h>
#include <cstdint>

// NOTE R8: identical to R7 submission — R7 hit a broker/container infra
// failure ("GB300 container failed twice") and never ran. Resubmitting to
// get the clean measurement for the 3-launch design.

#define NG    1024
#define DIM   128
#define HID   512
#define NREP  16
#define EB    1184     // edge blocks in fused kernel

// ---- scratch (no allocations allowed) ----
__device__ float    d_escratch[NREP * NG * DIM];   // 8 MB replicated edge sums
__device__ unsigned d_ecnt[NREP * NG];             // replicated edge counts
__device__ float    d_node_mean[NG * DIM];
__device__ int      d_node_start[NG + 1];

// ---------------------------------------------------------------------------
__device__ __forceinline__ int load_idx(const void* p, long long i, int idx64) {
    return idx64 ? (int)((const long long*)p)[i] : ((const int*)p)[i];
}
// dtype probe on edge_index: node ids are random nonzero ints, so
// all-zero odd 32-bit words <=> int64 storage.
__device__ __forceinline__ int probe_idx64(const void* edge_index) {
    const int* w = (const int*)edge_index;
    int all_zero = 1;
    #pragma unroll
    for (int i = 1; i < 128; i += 2) all_zero &= (w[i] == 0);
    return all_zero;
}

// ---------------------------------------------------------------------------
// K1: zero edge scratch + counts; spare blocks compute node_start boundaries.
// ---------------------------------------------------------------------------
__global__ void __launch_bounds__(256) zero_kernel(
        const void* __restrict__ batch,
        const void* __restrict__ edge_index,
        int n_nodes) {
    int b = blockIdx.x, tid = threadIdx.x;
    if (b < 2048) {
        int i = b * 256 + tid;                      // 524288 float4 = 8 MB
        ((float4*)d_escratch)[i] = make_float4(0.f, 0.f, 0.f, 0.f);
        if (i < NREP * NG) d_ecnt[i] = 0u;
    } else {
        int g = (b - 2048) * 256 + tid;             // 5 blocks cover 1025
        if (g <= NG) {
            int idx64 = probe_idx64(edge_index);
            int lo = 0, hi = n_nodes;
            while (lo < hi) {
                int m = (lo + hi) >> 1;
                if (load_idx(batch, m, idx64) < g) lo = m + 1; else hi = m;
            }
            d_node_start[g] = lo;
        }
    }
}

// ---------------------------------------------------------------------------
// K2: blocks 0..EB-1  -> edge scatter-accumulate (warp per edge row, red.v4)
//     blocks EB..     -> node mean (block per graph, contiguous rows)
// ---------------------------------------------------------------------------
__global__ void __launch_bounds__(256) edgenode_kernel(
        const float* __restrict__ edge_attr,
        const float* __restrict__ x,
        const void* __restrict__ edge_index,
        const void* __restrict__ batch,
        int n_edges) {
    int b = blockIdx.x, tid = threadIdx.x;
    int lane = tid & 31;

    if (b < EB) {
        __shared__ int s_idx64;
        if (tid == 0) s_idx64 = probe_idx64(edge_index);
        __syncthreads();
        int idx64 = s_idx64;

        int warp_g = (b * 256 + tid) >> 5;
        int nwarps = (EB * 256) >> 5;
        int rep    = warp_g & (NREP - 1);

        for (int e = warp_g; e < n_edges; e += nwarps) {
            int g = 0;
            if (lane == 0) {
                int src = load_idx(edge_index, e, idx64);   // row 0 of edge_index
                g = load_idx(batch, src, idx64);            // batch L2-resident
            }
            g = __shfl_sync(0xffffffffu, g, 0);

            float4 v = ((const float4*)(edge_attr + (size_t)e * DIM))[lane];
            float* dst = d_escratch + ((size_t)rep * NG + g) * DIM + lane * 4;
            asm volatile("red.global.add.v4.f32 [%0], {%1,%2,%3,%4};"
                         :: "l"(dst), "f"(v.x), "f"(v.y), "f"(v.z), "f"(v.w)
                         : "memory");
            if (lane == 0) atomicAdd(&d_ecnt[rep * NG + g], 1u);
        }
    } else {
        // node mean: graph g's rows are contiguous in x (batch is sorted)
        int g = b - EB;
        int s = d_node_start[g], e = d_node_start[g + 1];
        int cnt = e - s;
        int w = tid >> 5;

        const float4* xr = (const float4*)x;
        float4 acc = make_float4(0.f, 0.f, 0.f, 0.f);
        for (int n = s + w; n < e; n += 8) {
            float4 v = xr[(size_t)n * 32 + lane];
            acc.x += v.x; acc.y += v.y; acc.z += v.z; acc.w += v.w;
        }
        __shared__ float4 s_red[8][32];
        s_red[w][lane] = acc;
        __syncthreads();
        if (w == 0) {
            float4 t = s_red[0][lane];
            #pragma unroll
            for (int i = 1; i < 8; i++) {
                float4 q = s_red[i][lane];
                t.x += q.x; t.y += q.y; t.z += q.z; t.w += q.w;
            }
            float inv = 1.0f / (float)(cnt > 0 ? cnt : 1);
            t.x *= inv; t.y *= inv; t.z *= inv; t.w *= inv;
            ((float4*)(d_node_mean + (size_t)g * DIM))[lane] = t;
        }
    }
}

// ---------------------------------------------------------------------------
// K3: replica-reduce + MLP + residual + LayerNorm.
// 128 blocks x 8 graphs, 512 threads (16 warps), deep load pipelining.
// ---------------------------------------------------------------------------
__global__ void __launch_bounds__(512) mlp_kernel(
        const float* __restrict__ u,
        const float* __restrict__ W1, const float* __restrict__ b1,
        const float* __restrict__ W2, const float* __restrict__ b2,
        const float* __restrict__ gamma, const float* __restrict__ beta,
        float* __restrict__ out) {
    __shared__ float inp[8][3 * DIM];
    __shared__ float hbuf[8][HID];
    __shared__ float ysm[8][DIM];
    __shared__ float s_ecnt[8];

    int tid = threadIdx.x;
    int g0  = blockIdx.x * 8;

    if (tid < 8) {
        unsigned c = 0;
        #pragma unroll
        for (int r = 0; r < NREP; r++) c += d_ecnt[r * NG + g0 + tid];
        s_ecnt[tid] = 1.0f / (float)(c > 0u ? c : 1u);
    }
    __syncthreads();

    // build input rows: [u | edge_mean | node_mean]
    for (int idx = tid; idx < 8 * DIM; idx += 512) {
        int g = idx >> 7, d = idx & (DIM - 1);
        int gg = g0 + g;
        float es = 0.f;
        #pragma unroll
        for (int r = 0; r < NREP; r++)
            es += d_escratch[((size_t)r * NG + gg) * DIM + d];
        inp[g][d]           = u[(size_t)gg * DIM + d];
        inp[g][DIM + d]     = es * s_ecnt[g];
        inp[g][2 * DIM + d] = d_node_mean[(size_t)gg * DIM + d];
    }
    __syncthreads();

    // ---- layer 1: thread owns hidden col tid; 8-deep weight prefetch ----
    {
        float acc[8];
        float bb = b1[tid];
        #pragma unroll
        for (int g = 0; g < 8; g++) acc[g] = bb;

        float wcur[8], wnxt[8];
        #pragma unroll
        for (int kk = 0; kk < 8; kk++) wcur[kk] = W1[(size_t)kk * HID + tid];

        for (int k = 0; k < 3 * DIM; k += 8) {
            if (k + 8 < 3 * DIM) {
                #pragma unroll
                for (int kk = 0; kk < 8; kk++)
                    wnxt[kk] = W1[(size_t)(k + 8 + kk) * HID + tid];
            }
            #pragma unroll
            for (int kk = 0; kk < 8; kk++) {
                float wv = wcur[kk];
                #pragma unroll
                for (int g = 0; g < 8; g++)
                    acc[g] = fmaf(inp[g][k + kk], wv, acc[g]);
            }
            #pragma unroll
            for (int kk = 0; kk < 8; kk++) wcur[kk] = wnxt[kk];
        }
        #pragma unroll
        for (int g = 0; g < 8; g++)
            hbuf[g][tid] = fmaxf(acc[g], 0.f);
    }
    __syncthreads();

    // ---- layer 2: thread owns (graph tid>>6, float2 cols); pipelined ----
    {
        int g  = tid >> 6;            // 8 graphs x 64 threads
        int c0 = (tid & 63) * 2;      // 2 output cols per thread
        float2 acc = *(const float2*)&b2[c0];

        float2 wcur[8], wnxt[8];
        #pragma unroll
        for (int kk = 0; kk < 8; kk++)
            wcur[kk] = *(const float2*)&W2[(size_t)kk * DIM + c0];

        for (int k = 0; k < HID; k += 8) {
            if (k + 8 < HID) {
                #pragma unroll
                for (int kk = 0; kk < 8; kk++)
                    wnxt[kk] = *(const float2*)&W2[(size_t)(k + 8 + kk) * DIM + c0];
            }
            #pragma unroll
            for (int kk = 0; kk < 8; kk++) {
                float hv = hbuf[g][k + kk];
                acc.x = fmaf(hv, wcur[kk].x, acc.x);
                acc.y = fmaf(hv, wcur[kk].y, acc.y);
            }
            #pragma unroll
            for (int kk = 0; kk < 8; kk++) wcur[kk] = wnxt[kk];
        }
        *(float2*)&ysm[g][c0] = acc;
    }
    __syncthreads();

    // ---- residual + layernorm: warps 0..7, one graph each ----
    {
        int w = tid >> 5, lane = tid & 31;
        if (w < 8) {
            int gg = g0 + w;
            float4 v  = *(const float4*)&ysm[w][lane * 4];
            float4 uu = *(const float4*)&u[(size_t)gg * DIM + lane * 4];
            v.x += uu.x; v.y += uu.y; v.z += uu.z; v.w += uu.w;

            float sm = v.x + v.y + v.z + v.w;
            #pragma unroll
            for (int off = 16; off; off >>= 1) sm += __shfl_xor_sync(0xffffffffu, sm, off);
            float mu = sm * (1.0f / DIM);

            float dx = v.x - mu, dy = v.y - mu, dz = v.z - mu, dw = v.w - mu;
            float sq = dx * dx + dy * dy + dz * dz + dw * dw;
            #pragma unroll
            for (int off = 16; off; off >>= 1) sq += __shfl_xor_sync(0xffffffffu, sq, off);
            float rs = rsqrtf(sq * (1.0f / DIM) + 1e-5f);

            float4 gm = *(const float4*)&gamma[lane * 4];
            float4 bt = *(const float4*)&beta[lane * 4];
            float4 o;
            o.x = dx * rs * gm.x + bt.x;
            o.y = dy * rs * gm.y + bt.y;
            o.z = dz * rs * gm.z + bt.z;
            o.w = dw * rs * gm.w + bt.w;
            *(float4*)&out[(size_t)gg * DIM + lane * 4] = o;
        }
    }
}

// ---------------------------------------------------------------------------
extern "C" void kernel_launch(void* const* d_in, const int* in_sizes, int n_in,
                              void* d_out, int out_size) {
    const float* x         = (const float*)d_in[0];
    const float* edge_attr = (const float*)d_in[1];
    const float* u         = (const float*)d_in[2];
    const float* W1        = (const float*)d_in[3];
    const float* b1        = (const float*)d_in[4];
    const float* W2        = (const float*)d_in[5];
    const float* b2        = (const float*)d_in[6];
    const float* gamma     = (const float*)d_in[7];
    const float* beta      = (const float*)d_in[8];
    const void* edge_index = d_in[9];
    const void* batch      = d_in[10];

    int n_edges = in_sizes[9] / 2;
    int n_nodes = in_sizes[10];
    float* out = (float*)d_out;

    zero_kernel<<<2053, 256>>>(batch, edge_index, n_nodes);                        // 1
    edgenode_kernel<<<EB + NG, 256>>>(edge_attr, x, edge_index, batch, n_edges);   // 2
    mlp_kernel<<<NG / 8, 512>>>(u, W1, b1, W2, b2, gamma, beta, out);              // 3
}

// round 10
// speedup vs baseline: 1.7710x; 1.2438x over previous
#include <cuda_runtime.h>
#include <cstdint>

#define NG    1024
#define DIM   128
#define HID   512
#define NREP  16
#define EB    1184     // edge blocks in fused kernel

// ---- scratch (no allocations allowed) ----
// Zero-initialized at module load; mlp_kernel re-zeroes after consuming, so
// every kernel_launch call observes zeroed scratch (graph-replay safe).
__device__ float    d_escratch[NREP * NG * DIM];   // 8 MB replicated edge sums
__device__ unsigned d_ecnt[NREP * NG];             // replicated edge counts
__device__ float    d_node_mean[NG * DIM];

// ---------------------------------------------------------------------------
__device__ __forceinline__ int load_idx(const void* p, long long i, int idx64) {
    return idx64 ? (int)((const long long*)p)[i] : ((const int*)p)[i];
}
// dtype probe on edge_index: node ids are random nonzero ints, so
// all-zero odd 32-bit words <=> int64 storage.
__device__ __forceinline__ int probe_idx64(const void* edge_index) {
    const int* w = (const int*)edge_index;
    int all_zero = 1;
    #pragma unroll
    for (int i = 1; i < 128; i += 2) all_zero &= (w[i] == 0);
    return all_zero;
}

// red.global.add.v4 WITHOUT a memory clobber: ordering vs other memory ops is
// irrelevant (atomic, fire-and-forget); register deps keep it correct, and the
// compiler is free to overlap subsequent loads.
__device__ __forceinline__ void red_add_v4(float* dst, float4 v) {
    asm volatile("red.global.add.v4.f32 [%0], {%1,%2,%3,%4};"
                 :: "l"(dst), "f"(v.x), "f"(v.y), "f"(v.z), "f"(v.w));
}

// ---------------------------------------------------------------------------
// K1: blocks 0..EB-1 -> edge scatter-accumulate (warp per edge row, 2-way ILP)
//     blocks EB..    -> node mean (block per graph, self-computed bounds)
// ---------------------------------------------------------------------------
__global__ void __launch_bounds__(256) edgenode_kernel(
        const float* __restrict__ edge_attr,
        const float* __restrict__ x,
        const void* __restrict__ edge_index,
        const void* __restrict__ batch,
        int n_edges, int n_nodes) {
    int b = blockIdx.x, tid = threadIdx.x;
    int lane = tid & 31;

    if (b < EB) {
        __shared__ int s_idx64;
        if (tid == 0) s_idx64 = probe_idx64(edge_index);
        __syncthreads();
        int idx64 = s_idx64;

        int warp_g = (b * 256 + tid) >> 5;
        int nwarps = (EB * 256) >> 5;
        const float4* ea = (const float4*)edge_attr;

        for (int e = warp_g * 2; e < n_edges; e += nwarps * 2) {
            int has1 = (e + 1 < n_edges);
            int g0 = 0, g1 = 0;
            if (lane == 0) {
                g0 = load_idx(batch, load_idx(edge_index, e, idx64), idx64);
                if (has1)
                    g1 = load_idx(batch, load_idx(edge_index, e + 1, idx64), idx64);
            }
            g0 = __shfl_sync(0xffffffffu, g0, 0);
            g1 = __shfl_sync(0xffffffffu, g1, 0);

            int rep = (warp_g + (e >> 1)) & (NREP - 1);

            float4 v0 = ea[(size_t)e * 32 + lane];
            float4 v1 = has1 ? ea[(size_t)(e + 1) * 32 + lane]
                             : make_float4(0.f, 0.f, 0.f, 0.f);

            red_add_v4(d_escratch + ((size_t)rep * NG + g0) * DIM + lane * 4, v0);
            if (has1)
                red_add_v4(d_escratch + ((size_t)rep * NG + g1) * DIM + lane * 4, v1);
            if (lane == 0) {
                atomicAdd(&d_ecnt[rep * NG + g0], 1u);
                if (has1) atomicAdd(&d_ecnt[rep * NG + g1], 1u);
            }
        }
    } else {
        // node mean: graph g's rows are contiguous in x (batch is sorted)
        int g = b - EB;
        __shared__ int s_bound[2];
        if (tid < 2) {
            int idx64 = probe_idx64(edge_index);
            int target = g + tid;
            int lo = 0, hi = n_nodes;
            while (lo < hi) {
                int m = (lo + hi) >> 1;
                if (load_idx(batch, m, idx64) < target) lo = m + 1; else hi = m;
            }
            s_bound[tid] = lo;
        }
        __syncthreads();
        int s = s_bound[0], e = s_bound[1];
        int cnt = e - s;
        int w = tid >> 5;

        const float4* xr = (const float4*)x;
        float4 acc = make_float4(0.f, 0.f, 0.f, 0.f);
        for (int n = s + w; n < e; n += 8) {
            float4 v = xr[(size_t)n * 32 + lane];
            acc.x += v.x; acc.y += v.y; acc.z += v.z; acc.w += v.w;
        }
        __shared__ float4 s_red[8][32];
        s_red[w][lane] = acc;
        __syncthreads();
        if (w == 0) {
            float4 t = s_red[0][lane];
            #pragma unroll
            for (int i = 1; i < 8; i++) {
                float4 q = s_red[i][lane];
                t.x += q.x; t.y += q.y; t.z += q.z; t.w += q.w;
            }
            float inv = 1.0f / (float)(cnt > 0 ? cnt : 1);
            t.x *= inv; t.y *= inv; t.z *= inv; t.w *= inv;
            ((float4*)(d_node_mean + (size_t)g * DIM))[lane] = t;
        }
    }
}

// ---------------------------------------------------------------------------
// K2: replica-reduce + MLP + residual + LayerNorm + scratch re-zero.
// 128 blocks x 8 graphs, 512 threads (16 warps), deep load pipelining.
// ---------------------------------------------------------------------------
__global__ void __launch_bounds__(512) mlp_kernel(
        const float* __restrict__ u,
        const float* __restrict__ W1, const float* __restrict__ b1,
        const float* __restrict__ W2, const float* __restrict__ b2,
        const float* __restrict__ gamma, const float* __restrict__ beta,
        float* __restrict__ out) {
    __shared__ float inp[8][3 * DIM];
    __shared__ float hbuf[8][HID];
    __shared__ float ysm[8][DIM];
    __shared__ float s_ecnt[8];

    int tid = threadIdx.x;
    int g0  = blockIdx.x * 8;

    if (tid < 8) {
        unsigned c = 0;
        #pragma unroll
        for (int r = 0; r < NREP; r++) c += d_ecnt[r * NG + g0 + tid];
        s_ecnt[tid] = 1.0f / (float)(c > 0u ? c : 1u);
    }
    __syncthreads();

    // build input rows: [u | edge_mean | node_mean]
    for (int idx = tid; idx < 8 * DIM; idx += 512) {
        int g = idx >> 7, d = idx & (DIM - 1);
        int gg = g0 + g;
        float es = 0.f;
        #pragma unroll
        for (int r = 0; r < NREP; r++)
            es += d_escratch[((size_t)r * NG + gg) * DIM + d];
        inp[g][d]           = u[(size_t)gg * DIM + d];
        inp[g][DIM + d]     = es * s_ecnt[g];
        inp[g][2 * DIM + d] = d_node_mean[(size_t)gg * DIM + d];
    }
    __syncthreads();

    // re-zero the scratch this block consumed (stores overlap layer 1)
    {
        float4 z = make_float4(0.f, 0.f, 0.f, 0.f);
        // 16 reps x (8 graphs * 128 floats contiguous) = 16 x 256 float4
        for (int idx = tid; idx < NREP * 256; idx += 512) {
            int r = idx >> 8, off = idx & 255;
            ((float4*)(d_escratch + ((size_t)r * NG + g0) * DIM))[off] = z;
        }
        if (tid < NREP * 8)
            d_ecnt[(tid >> 3) * NG + g0 + (tid & 7)] = 0u;
    }

    // ---- layer 1: thread owns hidden col tid; 8-deep weight prefetch ----
    {
        float acc[8];
        float bb = b1[tid];
        #pragma unroll
        for (int g = 0; g < 8; g++) acc[g] = bb;

        float wcur[8], wnxt[8];
        #pragma unroll
        for (int kk = 0; kk < 8; kk++) wcur[kk] = W1[(size_t)kk * HID + tid];

        for (int k = 0; k < 3 * DIM; k += 8) {
            if (k + 8 < 3 * DIM) {
                #pragma unroll
                for (int kk = 0; kk < 8; kk++)
                    wnxt[kk] = W1[(size_t)(k + 8 + kk) * HID + tid];
            }
            #pragma unroll
            for (int kk = 0; kk < 8; kk++) {
                float wv = wcur[kk];
                #pragma unroll
                for (int g = 0; g < 8; g++)
                    acc[g] = fmaf(inp[g][k + kk], wv, acc[g]);
            }
            #pragma unroll
            for (int kk = 0; kk < 8; kk++) wcur[kk] = wnxt[kk];
        }
        #pragma unroll
        for (int g = 0; g < 8; g++)
            hbuf[g][tid] = fmaxf(acc[g], 0.f);
    }
    __syncthreads();

    // ---- layer 2: thread owns (graph tid>>6, float2 cols); pipelined ----
    {
        int g  = tid >> 6;            // 8 graphs x 64 threads
        int c0 = (tid & 63) * 2;      // 2 output cols per thread
        float2 acc = *(const float2*)&b2[c0];

        float2 wcur[8], wnxt[8];
        #pragma unroll
        for (int kk = 0; kk < 8; kk++)
            wcur[kk] = *(const float2*)&W2[(size_t)kk * DIM + c0];

        for (int k = 0; k < HID; k += 8) {
            if (k + 8 < HID) {
                #pragma unroll
                for (int kk = 0; kk < 8; kk++)
                    wnxt[kk] = *(const float2*)&W2[(size_t)(k + 8 + kk) * DIM + c0];
            }
            #pragma unroll
            for (int kk = 0; kk < 8; kk++) {
                float hv = hbuf[g][k + kk];
                acc.x = fmaf(hv, wcur[kk].x, acc.x);
                acc.y = fmaf(hv, wcur[kk].y, acc.y);
            }
            #pragma unroll
            for (int kk = 0; kk < 8; kk++) wcur[kk] = wnxt[kk];
        }
        *(float2*)&ysm[g][c0] = acc;
    }
    __syncthreads();

    // ---- residual + layernorm: warps 0..7, one graph each ----
    {
        int w = tid >> 5, lane = tid & 31;
        if (w < 8) {
            int gg = g0 + w;
            float4 v  = *(const float4*)&ysm[w][lane * 4];
            float4 uu = *(const float4*)&u[(size_t)gg * DIM + lane * 4];
            v.x += uu.x; v.y += uu.y; v.z += uu.z; v.w += uu.w;

            float sm = v.x + v.y + v.z + v.w;
            #pragma unroll
            for (int off = 16; off; off >>= 1) sm += __shfl_xor_sync(0xffffffffu, sm, off);
            float mu = sm * (1.0f / DIM);

            float dx = v.x - mu, dy = v.y - mu, dz = v.z - mu, dw = v.w - mu;
            float sq = dx * dx + dy * dy + dz * dz + dw * dw;
            #pragma unroll
            for (int off = 16; off; off >>= 1) sq += __shfl_xor_sync(0xffffffffu, sq, off);
            float rs = rsqrtf(sq * (1.0f / DIM) + 1e-5f);

            float4 gm = *(const float4*)&gamma[lane * 4];
            float4 bt = *(const float4*)&beta[lane * 4];
            float4 o;
            o.x = dx * rs * gm.x + bt.x;
            o.y = dy * rs * gm.y + bt.y;
            o.z = dz * rs * gm.z + bt.z;
            o.w = dw * rs * gm.w + bt.w;
            *(float4*)&out[(size_t)gg * DIM + lane * 4] = o;
        }
    }
}

// ---------------------------------------------------------------------------
extern "C" void kernel_launch(void* const* d_in, const int* in_sizes, int n_in,
                              void* d_out, int out_size) {
    const float* x         = (const float*)d_in[0];
    const float* edge_attr = (const float*)d_in[1];
    const float* u         = (const float*)d_in[2];
    const float* W1        = (const float*)d_in[3];
    const float* b1        = (const float*)d_in[4];
    const float* W2        = (const float*)d_in[5];
    const float* b2        = (const float*)d_in[6];
    const float* gamma     = (const float*)d_in[7];
    const float* beta      = (const float*)d_in[8];
    const void* edge_index = d_in[9];
    const void* batch      = d_in[10];

    int n_edges = in_sizes[9] / 2;
    int n_nodes = in_sizes[10];
    float* out = (float*)d_out;

    edgenode_kernel<<<EB + NG, 256>>>(edge_attr, x, edge_index, batch,
                                      n_edges, n_nodes);                   // 1
    mlp_kernel<<<NG / 8, 512>>>(u, W1, b1, W2, b2, gamma, beta, out);      // 2
}

// round 11
// speedup vs baseline: 1.8677x; 1.0546x over previous
#include <cuda_runtime.h>
#include <cstdint>

#define NG    1024
#define DIM   128
#define HID   512
#define NREP  16
#define EB    1184     // edge blocks in fused kernel
#define GPB   4        // graphs per mlp block

// ---- scratch (no allocations allowed) ----
// Zero-initialized at module load; mlp_kernel re-zeroes after consuming, so
// every kernel_launch call observes zeroed scratch (graph-replay safe).
__device__ float    d_escratch[NREP * NG * DIM];   // 8 MB replicated edge sums
__device__ unsigned d_ecnt[NREP * NG];             // replicated edge counts
__device__ float    d_node_mean[NG * DIM];

// ---------------------------------------------------------------------------
__device__ __forceinline__ int load_idx(const void* p, long long i, int idx64) {
    return idx64 ? (int)((const long long*)p)[i] : ((const int*)p)[i];
}
// dtype probe on edge_index: node ids are random nonzero ints, so
// all-zero odd 32-bit words <=> int64 storage.
__device__ __forceinline__ int probe_idx64(const void* edge_index) {
    const int* w = (const int*)edge_index;
    int all_zero = 1;
    #pragma unroll
    for (int i = 1; i < 128; i += 2) all_zero &= (w[i] == 0);
    return all_zero;
}

// red.global.add.v4 WITHOUT a memory clobber: fire-and-forget atomic; register
// deps keep it correct and the compiler can overlap subsequent loads.
__device__ __forceinline__ void red_add_v4(float* dst, float4 v) {
    asm volatile("red.global.add.v4.f32 [%0], {%1,%2,%3,%4};"
                 :: "l"(dst), "f"(v.x), "f"(v.y), "f"(v.z), "f"(v.w));
}

// ---------------------------------------------------------------------------
// K1: blocks 0..EB-1 -> edge scatter-accumulate (warp per edge row, 2-way ILP)
//     blocks EB..    -> node mean (block per graph, self-computed bounds)
// ---------------------------------------------------------------------------
__global__ void __launch_bounds__(256) edgenode_kernel(
        const float* __restrict__ edge_attr,
        const float* __restrict__ x,
        const void* __restrict__ edge_index,
        const void* __restrict__ batch,
        int n_edges, int n_nodes) {
    int b = blockIdx.x, tid = threadIdx.x;
    int lane = tid & 31;

    if (b < EB) {
        __shared__ int s_idx64;
        if (tid == 0) s_idx64 = probe_idx64(edge_index);
        __syncthreads();
        int idx64 = s_idx64;

        int warp_g = (b * 256 + tid) >> 5;
        int nwarps = (EB * 256) >> 5;
        const float4* ea = (const float4*)edge_attr;

        for (int e = warp_g * 2; e < n_edges; e += nwarps * 2) {
            int has1 = (e + 1 < n_edges);
            int g0 = 0, g1 = 0;
            if (lane == 0) {
                g0 = load_idx(batch, load_idx(edge_index, e, idx64), idx64);
                if (has1)
                    g1 = load_idx(batch, load_idx(edge_index, e + 1, idx64), idx64);
            }
            g0 = __shfl_sync(0xffffffffu, g0, 0);
            g1 = __shfl_sync(0xffffffffu, g1, 0);

            int rep = (warp_g + (e >> 1)) & (NREP - 1);

            float4 v0 = ea[(size_t)e * 32 + lane];
            float4 v1 = has1 ? ea[(size_t)(e + 1) * 32 + lane]
                             : make_float4(0.f, 0.f, 0.f, 0.f);

            red_add_v4(d_escratch + ((size_t)rep * NG + g0) * DIM + lane * 4, v0);
            if (has1)
                red_add_v4(d_escratch + ((size_t)rep * NG + g1) * DIM + lane * 4, v1);
            if (lane == 0) {
                atomicAdd(&d_ecnt[rep * NG + g0], 1u);
                if (has1) atomicAdd(&d_ecnt[rep * NG + g1], 1u);
            }
        }
    } else {
        // node mean: graph g's rows are contiguous in x (batch is sorted)
        int g = b - EB;
        __shared__ int s_bound[2];
        if (tid < 2) {
            int idx64 = probe_idx64(edge_index);
            int target = g + tid;
            int lo = 0, hi = n_nodes;
            while (lo < hi) {
                int m = (lo + hi) >> 1;
                if (load_idx(batch, m, idx64) < target) lo = m + 1; else hi = m;
            }
            s_bound[tid] = lo;
        }
        __syncthreads();
        int s = s_bound[0], e = s_bound[1];
        int cnt = e - s;
        int w = tid >> 5;

        const float4* xr = (const float4*)x;
        float4 acc = make_float4(0.f, 0.f, 0.f, 0.f);
        for (int n = s + w; n < e; n += 8) {
            float4 v = xr[(size_t)n * 32 + lane];
            acc.x += v.x; acc.y += v.y; acc.z += v.z; acc.w += v.w;
        }
        __shared__ float4 s_red[8][32];
        s_red[w][lane] = acc;
        __syncthreads();
        if (w == 0) {
            float4 t = s_red[0][lane];
            #pragma unroll
            for (int i = 1; i < 8; i++) {
                float4 q = s_red[i][lane];
                t.x += q.x; t.y += q.y; t.z += q.z; t.w += q.w;
            }
            float inv = 1.0f / (float)(cnt > 0 ? cnt : 1);
            t.x *= inv; t.y *= inv; t.z *= inv; t.w *= inv;
            ((float4*)(d_node_mean + (size_t)g * DIM))[lane] = t;
        }
    }
}

// ---------------------------------------------------------------------------
// K2: replica-reduce + MLP + residual + LayerNorm + scratch re-zero.
// 256 blocks x 4 graphs, 512 threads; float4 LDS; 8-deep weight prefetch.
// ---------------------------------------------------------------------------
__global__ void __launch_bounds__(512) mlp_kernel(
        const float* __restrict__ u,
        const float* __restrict__ W1, const float* __restrict__ b1,
        const float* __restrict__ W2, const float* __restrict__ b2,
        const float* __restrict__ gamma, const float* __restrict__ beta,
        float* __restrict__ out) {
    __shared__ float inp[GPB][3 * DIM];
    __shared__ float hbuf[GPB][HID];
    __shared__ float ysm[GPB][DIM];
    __shared__ float s_ecnt[GPB];

    int tid = threadIdx.x;
    int g0  = blockIdx.x * GPB;

    if (tid < GPB) {
        unsigned c = 0;
        #pragma unroll
        for (int r = 0; r < NREP; r++) c += d_ecnt[r * NG + g0 + tid];
        s_ecnt[tid] = 1.0f / (float)(c > 0u ? c : 1u);
    }
    __syncthreads();

    // build input rows: [u | edge_mean | node_mean]   (GPB*384 = 1536 elems)
    for (int idx = tid; idx < GPB * DIM; idx += 512) {
        int g = idx >> 7, d = idx & (DIM - 1);
        int gg = g0 + g;
        float es = 0.f;
        #pragma unroll
        for (int r = 0; r < NREP; r++)
            es += d_escratch[((size_t)r * NG + gg) * DIM + d];
        inp[g][d]           = u[(size_t)gg * DIM + d];
        inp[g][DIM + d]     = es * s_ecnt[g];
        inp[g][2 * DIM + d] = d_node_mean[(size_t)gg * DIM + d];
    }
    __syncthreads();

    // re-zero the scratch this block consumed (stores overlap layer 1)
    {
        float4 z = make_float4(0.f, 0.f, 0.f, 0.f);
        // NREP reps x (GPB graphs * 128 floats contiguous) = NREP x 128 float4
        for (int idx = tid; idx < NREP * GPB * 32; idx += 512) {
            int r = idx >> 7, off = idx & 127;
            ((float4*)(d_escratch + ((size_t)r * NG + g0) * DIM))[off] = z;
        }
        if (tid < NREP * GPB)
            d_ecnt[(tid >> 2) * NG + g0 + (tid & 3)] = 0u;
    }

    // ---- layer 1: thread owns hidden col tid; float4 LDS + 8-deep prefetch
    {
        float acc[GPB];
        float bb = b1[tid];
        #pragma unroll
        for (int g = 0; g < GPB; g++) acc[g] = bb;

        float wcur[8], wnxt[8];
        #pragma unroll
        for (int kk = 0; kk < 8; kk++) wcur[kk] = W1[(size_t)kk * HID + tid];

        for (int k = 0; k < 3 * DIM; k += 8) {
            if (k + 8 < 3 * DIM) {
                #pragma unroll
                for (int kk = 0; kk < 8; kk++)
                    wnxt[kk] = W1[(size_t)(k + 8 + kk) * HID + tid];
            }
            float4 iv[GPB][2];
            #pragma unroll
            for (int g = 0; g < GPB; g++) {
                iv[g][0] = *(const float4*)&inp[g][k];
                iv[g][1] = *(const float4*)&inp[g][k + 4];
            }
            #pragma unroll
            for (int kk = 0; kk < 8; kk++) {
                float wv = wcur[kk];
                #pragma unroll
                for (int g = 0; g < GPB; g++) {
                    float xv = (kk < 4)
                        ? ((kk == 0) ? iv[g][0].x : (kk == 1) ? iv[g][0].y
                         : (kk == 2) ? iv[g][0].z : iv[g][0].w)
                        : ((kk == 4) ? iv[g][1].x : (kk == 5) ? iv[g][1].y
                         : (kk == 6) ? iv[g][1].z : iv[g][1].w);
                    acc[g] = fmaf(xv, wv, acc[g]);
                }
            }
            #pragma unroll
            for (int kk = 0; kk < 8; kk++) wcur[kk] = wnxt[kk];
        }
        #pragma unroll
        for (int g = 0; g < GPB; g++)
            hbuf[g][tid] = fmaxf(acc[g], 0.f);
    }
    __syncthreads();

    // ---- layer 2: thread owns (graph tid>>7, col tid&127); pipelined ----
    {
        int g = tid >> 7;             // 4 graphs x 128 threads
        int c = tid & 127;            // one output col per thread
        float acc = b2[c];

        float wcur[8], wnxt[8];
        #pragma unroll
        for (int kk = 0; kk < 8; kk++)
            wcur[kk] = W2[(size_t)kk * DIM + c];

        for (int k = 0; k < HID; k += 8) {
            if (k + 8 < HID) {
                #pragma unroll
                for (int kk = 0; kk < 8; kk++)
                    wnxt[kk] = W2[(size_t)(k + 8 + kk) * DIM + c];
            }
            float4 h0 = *(const float4*)&hbuf[g][k];
            float4 h1 = *(const float4*)&hbuf[g][k + 4];
            acc = fmaf(h0.x, wcur[0], acc);
            acc = fmaf(h0.y, wcur[1], acc);
            acc = fmaf(h0.z, wcur[2], acc);
            acc = fmaf(h0.w, wcur[3], acc);
            acc = fmaf(h1.x, wcur[4], acc);
            acc = fmaf(h1.y, wcur[5], acc);
            acc = fmaf(h1.z, wcur[6], acc);
            acc = fmaf(h1.w, wcur[7], acc);
            #pragma unroll
            for (int kk = 0; kk < 8; kk++) wcur[kk] = wnxt[kk];
        }
        ysm[g][c] = acc;
    }
    __syncthreads();

    // ---- residual + layernorm: warps 0..3, one graph each ----
    {
        int w = tid >> 5, lane = tid & 31;
        if (w < GPB) {
            int gg = g0 + w;
            float4 v  = *(const float4*)&ysm[w][lane * 4];
            float4 uu = *(const float4*)&u[(size_t)gg * DIM + lane * 4];
            v.x += uu.x; v.y += uu.y; v.z += uu.z; v.w += uu.w;

            float sm = v.x + v.y + v.z + v.w;
            #pragma unroll
            for (int off = 16; off; off >>= 1) sm += __shfl_xor_sync(0xffffffffu, sm, off);
            float mu = sm * (1.0f / DIM);

            float dx = v.x - mu, dy = v.y - mu, dz = v.z - mu, dw = v.w - mu;
            float sq = dx * dx + dy * dy + dz * dz + dw * dw;
            #pragma unroll
            for (int off = 16; off; off >>= 1) sq += __shfl_xor_sync(0xffffffffu, sq, off);
            float rs = rsqrtf(sq * (1.0f / DIM) + 1e-5f);

            float4 gm = *(const float4*)&gamma[lane * 4];
            float4 bt = *(const float4*)&beta[lane * 4];
            float4 o;
            o.x = dx * rs * gm.x + bt.x;
            o.y = dy * rs * gm.y + bt.y;
            o.z = dz * rs * gm.z + bt.z;
            o.w = dw * rs * gm.w + bt.w;
            *(float4*)&out[(size_t)gg * DIM + lane * 4] = o;
        }
    }
}

// ---------------------------------------------------------------------------
extern "C" void kernel_launch(void* const* d_in, const int* in_sizes, int n_in,
                              void* d_out, int out_size) {
    const float* x         = (const float*)d_in[0];
    const float* edge_attr = (const float*)d_in[1];
    const float* u         = (const float*)d_in[2];
    const float* W1        = (const float*)d_in[3];
    const float* b1        = (const float*)d_in[4];
    const float* W2        = (const float*)d_in[5];
    const float* b2        = (const float*)d_in[6];
    const float* gamma     = (const float*)d_in[7];
    const float* beta      = (const float*)d_in[8];
    const void* edge_index = d_in[9];
    const void* batch      = d_in[10];

    int n_edges = in_sizes[9] / 2;
    int n_nodes = in_sizes[10];
    float* out = (float*)d_out;

    edgenode_kernel<<<EB + NG, 256>>>(edge_attr, x, edge_index, batch,
                                      n_edges, n_nodes);                   // 1
    mlp_kernel<<<NG / GPB, 512>>>(u, W1, b1, W2, b2, gamma, beta, out);    // 2
}

// round 12
// speedup vs baseline: 1.9059x; 1.0205x over previous
#include <cuda_runtime.h>
#include <cstdint>

#define NG    1024
#define DIM   128
#define HID   512
#define NREP  4
#define EB    1184     // edge blocks in fused kernel

// ---- scratch (no allocations allowed) ----
// Zero-initialized at load; mlp2_kernel re-zeroes after the pipeline consumed
// it, so every kernel_launch call observes zeroed scratch (graph-replay safe).
__device__ float    d_escratch[NREP * NG * DIM];   // 2 MB replicated edge sums
__device__ unsigned d_ecnt[NREP * NG];             // replicated edge counts
__device__ float    d_node_mean[NG * DIM];
__device__ float    d_hbuf[NG * HID];              // hidden activations (2 MB)

// ---------------------------------------------------------------------------
__device__ __forceinline__ int load_idx(const void* p, long long i, int idx64) {
    return idx64 ? (int)((const long long*)p)[i] : ((const int*)p)[i];
}
// dtype probe on edge_index: node ids are random nonzero ints, so
// all-zero odd 32-bit words <=> int64 storage.
__device__ __forceinline__ int probe_idx64(const void* edge_index) {
    const int* w = (const int*)edge_index;
    int all_zero = 1;
    #pragma unroll
    for (int i = 1; i < 128; i += 2) all_zero &= (w[i] == 0);
    return all_zero;
}

// red.global.add.v4 WITHOUT a memory clobber: fire-and-forget atomic; register
// deps keep it correct and the compiler can overlap subsequent loads.
__device__ __forceinline__ void red_add_v4(float* dst, float4 v) {
    asm volatile("red.global.add.v4.f32 [%0], {%1,%2,%3,%4};"
                 :: "l"(dst), "f"(v.x), "f"(v.y), "f"(v.z), "f"(v.w));
}

// ---------------------------------------------------------------------------
// K1: blocks 0..EB-1 -> edge scatter-accumulate (warp per edge row, 2-way ILP)
//     blocks EB..    -> node mean (block per graph, self-computed bounds)
// ---------------------------------------------------------------------------
__global__ void __launch_bounds__(256) edgenode_kernel(
        const float* __restrict__ edge_attr,
        const float* __restrict__ x,
        const void* __restrict__ edge_index,
        const void* __restrict__ batch,
        int n_edges, int n_nodes) {
    int b = blockIdx.x, tid = threadIdx.x;
    int lane = tid & 31;

    if (b < EB) {
        __shared__ int s_idx64;
        if (tid == 0) s_idx64 = probe_idx64(edge_index);
        __syncthreads();
        int idx64 = s_idx64;

        int warp_g = (b * 256 + tid) >> 5;
        int nwarps = (EB * 256) >> 5;
        const float4* ea = (const float4*)edge_attr;

        for (int e = warp_g * 2; e < n_edges; e += nwarps * 2) {
            int has1 = (e + 1 < n_edges);
            int g0 = 0, g1 = 0;
            if (lane == 0) {
                g0 = load_idx(batch, load_idx(edge_index, e, idx64), idx64);
                if (has1)
                    g1 = load_idx(batch, load_idx(edge_index, e + 1, idx64), idx64);
            }
            g0 = __shfl_sync(0xffffffffu, g0, 0);
            g1 = __shfl_sync(0xffffffffu, g1, 0);

            int rep = (warp_g + (e >> 1)) & (NREP - 1);

            float4 v0 = ea[(size_t)e * 32 + lane];
            float4 v1 = has1 ? ea[(size_t)(e + 1) * 32 + lane]
                             : make_float4(0.f, 0.f, 0.f, 0.f);

            red_add_v4(d_escratch + ((size_t)rep * NG + g0) * DIM + lane * 4, v0);
            if (has1)
                red_add_v4(d_escratch + ((size_t)rep * NG + g1) * DIM + lane * 4, v1);
            if (lane == 0) {
                atomicAdd(&d_ecnt[rep * NG + g0], 1u);
                if (has1) atomicAdd(&d_ecnt[rep * NG + g1], 1u);
            }
        }
    } else {
        // node mean: graph g's rows are contiguous in x (batch is sorted)
        int g = b - EB;
        __shared__ int s_bound[2];
        if (tid < 2) {
            int idx64 = probe_idx64(edge_index);
            int target = g + tid;
            int lo = 0, hi = n_nodes;
            while (lo < hi) {
                int m = (lo + hi) >> 1;
                if (load_idx(batch, m, idx64) < target) lo = m + 1; else hi = m;
            }
            s_bound[tid] = lo;
        }
        __syncthreads();
        int s = s_bound[0], e = s_bound[1];
        int cnt = e - s;
        int w = tid >> 5;

        const float4* xr = (const float4*)x;
        float4 acc = make_float4(0.f, 0.f, 0.f, 0.f);
        for (int n = s + w; n < e; n += 8) {
            float4 v = xr[(size_t)n * 32 + lane];
            acc.x += v.x; acc.y += v.y; acc.z += v.z; acc.w += v.w;
        }
        __shared__ float4 s_red[8][32];
        s_red[w][lane] = acc;
        __syncthreads();
        if (w == 0) {
            float4 t = s_red[0][lane];
            #pragma unroll
            for (int i = 1; i < 8; i++) {
                float4 q = s_red[i][lane];
                t.x += q.x; t.y += q.y; t.z += q.z; t.w += q.w;
            }
            float inv = 1.0f / (float)(cnt > 0 ? cnt : 1);
            t.x *= inv; t.y *= inv; t.z *= inv; t.w *= inv;
            ((float4*)(d_node_mean + (size_t)g * DIM))[lane] = t;
        }
    }
}

// ---------------------------------------------------------------------------
// K2 (mlp1): h = relu(inp @ W1 + b1) with W1 staged in smem.
// 128 blocks = 8 hidden-slices (64 cols) x 16 graph-tiles (64 graphs).
// 256 threads: tx = tid&15 -> 4 cols, ty = tid>>4 -> 4 graphs. 6 k-chunks of 64.
// ---------------------------------------------------------------------------
__global__ void __launch_bounds__(256) mlp1_kernel(
        const float* __restrict__ u,
        const float* __restrict__ W1, const float* __restrict__ b1) {
    __shared__ float w1c[64 * 64];        // 16 KB: W1 chunk [64 k][64 cols]
    __shared__ float inps[64 * 65];       // 16.6 KB: inp [64 g][64 k + pad]
    __shared__ float s_inv[64];           // 1/edge_count per graph

    int bI = blockIdx.x;
    int sl = bI & 7;           // hidden slice
    int tI = bI >> 3;          // graph tile
    int gbase = tI * 64;
    int tid = threadIdx.x;
    int tx = tid & 15, ty = tid >> 4;

    if (tid < 64) {
        unsigned c = 0;
        #pragma unroll
        for (int r = 0; r < NREP; r++) c += d_ecnt[r * NG + gbase + tid];
        s_inv[tid] = 1.0f / (float)(c > 0u ? c : 1u);
    }

    float4 bb = *(const float4*)&b1[sl * 64 + tx * 4];
    float acc[4][4];
    #pragma unroll
    for (int gi = 0; gi < 4; gi++) {
        acc[gi][0] = bb.x; acc[gi][1] = bb.y; acc[gi][2] = bb.z; acc[gi][3] = bb.w;
    }

    for (int ch = 0; ch < 6; ch++) {
        int kc = ch * 64;
        __syncthreads();   // protect smem from previous chunk's readers

        // stage W1 chunk [64 rows][64 cols of this slice]
        #pragma unroll
        for (int p = 0; p < 4; p++) {
            int idx = tid + p * 256;
            int row = idx >> 4, cc = idx & 15;
            *(float4*)&w1c[row * 64 + cc * 4] =
                *(const float4*)&W1[(size_t)(kc + row) * HID + sl * 64 + cc * 4];
        }
        // stage inp chunk [64 graphs][64 features]
        #pragma unroll
        for (int p = 0; p < 4; p++) {
            int idx = tid + p * 256;
            int g = idx >> 4, kq = idx & 15;
            int gg = gbase + g;
            float4 v;
            if (ch < 2) {
                v = *(const float4*)&u[(size_t)gg * DIM + kc + kq * 4];
            } else if (ch < 4) {
                int col = kc - 128 + kq * 4;
                v = make_float4(0.f, 0.f, 0.f, 0.f);
                #pragma unroll
                for (int r = 0; r < NREP; r++) {
                    float4 q = *(const float4*)&d_escratch[((size_t)r * NG + gg) * DIM + col];
                    v.x += q.x; v.y += q.y; v.z += q.z; v.w += q.w;
                }
                float iv = s_inv[g];
                v.x *= iv; v.y *= iv; v.z *= iv; v.w *= iv;
            } else {
                v = *(const float4*)&d_node_mean[(size_t)gg * DIM + kc - 256 + kq * 4];
            }
            float* dst = &inps[g * 65 + kq * 4];
            dst[0] = v.x; dst[1] = v.y; dst[2] = v.z; dst[3] = v.w;
        }
        __syncthreads();

        // compute: 64 k x (4 graphs x 4 cols)
        #pragma unroll 4
        for (int kk = 0; kk < 64; kk++) {
            float4 wv = *(const float4*)&w1c[kk * 64 + tx * 4];
            float x0 = inps[(ty * 4 + 0) * 65 + kk];
            float x1 = inps[(ty * 4 + 1) * 65 + kk];
            float x2 = inps[(ty * 4 + 2) * 65 + kk];
            float x3 = inps[(ty * 4 + 3) * 65 + kk];
            acc[0][0] = fmaf(x0, wv.x, acc[0][0]); acc[0][1] = fmaf(x0, wv.y, acc[0][1]);
            acc[0][2] = fmaf(x0, wv.z, acc[0][2]); acc[0][3] = fmaf(x0, wv.w, acc[0][3]);
            acc[1][0] = fmaf(x1, wv.x, acc[1][0]); acc[1][1] = fmaf(x1, wv.y, acc[1][1]);
            acc[1][2] = fmaf(x1, wv.z, acc[1][2]); acc[1][3] = fmaf(x1, wv.w, acc[1][3]);
            acc[2][0] = fmaf(x2, wv.x, acc[2][0]); acc[2][1] = fmaf(x2, wv.y, acc[2][1]);
            acc[2][2] = fmaf(x2, wv.z, acc[2][2]); acc[2][3] = fmaf(x2, wv.w, acc[2][3]);
            acc[3][0] = fmaf(x3, wv.x, acc[3][0]); acc[3][1] = fmaf(x3, wv.y, acc[3][1]);
            acc[3][2] = fmaf(x3, wv.z, acc[3][2]); acc[3][3] = fmaf(x3, wv.w, acc[3][3]);
        }
    }

    // write h with relu (coalesced float4)
    #pragma unroll
    for (int gi = 0; gi < 4; gi++) {
        int gg = gbase + ty * 4 + gi;
        float4 o;
        o.x = fmaxf(acc[gi][0], 0.f); o.y = fmaxf(acc[gi][1], 0.f);
        o.z = fmaxf(acc[gi][2], 0.f); o.w = fmaxf(acc[gi][3], 0.f);
        *(float4*)&d_hbuf[(size_t)gg * HID + sl * 64 + tx * 4] = o;
    }
}

// ---------------------------------------------------------------------------
// K3 (mlp2): y = LayerNorm(h @ W2 + b2 + u) with W2 staged in smem.
// 64 blocks x 16 graphs, 256 threads. Warp w owns graphs (2w, 2w+1);
// lane owns 4 output cols. 8 k-chunks of 64. Also re-zeroes scratch.
// ---------------------------------------------------------------------------
__global__ void __launch_bounds__(256) mlp2_kernel(
        const float* __restrict__ u,
        const float* __restrict__ W2, const float* __restrict__ b2,
        const float* __restrict__ gamma, const float* __restrict__ beta,
        float* __restrict__ out) {
    __shared__ float w2c[64 * 128];    // 32 KB: W2 chunk [64 k][128 cols]
    __shared__ float hs[16 * 64];      // 4 KB: h chunk [16 g][64 k]

    int bI = blockIdx.x;
    int gbase = bI * 16;
    int tid = threadIdx.x;
    int w = tid >> 5, lane = tid & 31;
    int c0 = lane * 4;

    float4 bb = *(const float4*)&b2[c0];
    float4 a0 = bb, a1 = bb;   // graphs 2w and 2w+1

    for (int ch = 0; ch < 8; ch++) {
        int kc = ch * 64;
        __syncthreads();
        // stage W2 chunk
        #pragma unroll
        for (int p = 0; p < 8; p++) {
            int idx = tid + p * 256;
            int row = idx >> 5, cg = idx & 31;
            *(float4*)&w2c[row * 128 + cg * 4] =
                *(const float4*)&W2[(size_t)(kc + row) * DIM + cg * 4];
        }
        // stage h chunk for the 16 graphs
        {
            int g = tid >> 4, kq = tid & 15;
            *(float4*)&hs[g * 64 + kq * 4] =
                *(const float4*)&d_hbuf[(size_t)(gbase + g) * HID + kc + kq * 4];
        }
        __syncthreads();

        #pragma unroll 4
        for (int kk = 0; kk < 64; kk++) {
            float hv0 = hs[(2 * w) * 64 + kk];
            float hv1 = hs[(2 * w + 1) * 64 + kk];
            float4 wv = *(const float4*)&w2c[kk * 128 + c0];
            a0.x = fmaf(hv0, wv.x, a0.x); a0.y = fmaf(hv0, wv.y, a0.y);
            a0.z = fmaf(hv0, wv.z, a0.z); a0.w = fmaf(hv0, wv.w, a0.w);
            a1.x = fmaf(hv1, wv.x, a1.x); a1.y = fmaf(hv1, wv.y, a1.y);
            a1.z = fmaf(hv1, wv.z, a1.z); a1.w = fmaf(hv1, wv.w, a1.w);
        }
    }

    // residual + layernorm for both graphs of this warp
    float4 gm = *(const float4*)&gamma[c0];
    float4 bt = *(const float4*)&beta[c0];
    #pragma unroll
    for (int gi = 0; gi < 2; gi++) {
        int gg = gbase + 2 * w + gi;
        float4 v = (gi == 0) ? a0 : a1;
        float4 uu = *(const float4*)&u[(size_t)gg * DIM + c0];
        v.x += uu.x; v.y += uu.y; v.z += uu.z; v.w += uu.w;

        float sm = v.x + v.y + v.z + v.w;
        #pragma unroll
        for (int off = 16; off; off >>= 1) sm += __shfl_xor_sync(0xffffffffu, sm, off);
        float mu = sm * (1.0f / DIM);

        float dx = v.x - mu, dy = v.y - mu, dz = v.z - mu, dw = v.w - mu;
        float sq = dx * dx + dy * dy + dz * dz + dw * dw;
        #pragma unroll
        for (int off = 16; off; off >>= 1) sq += __shfl_xor_sync(0xffffffffu, sq, off);
        float rs = rsqrtf(sq * (1.0f / DIM) + 1e-5f);

        float4 o;
        o.x = dx * rs * gm.x + bt.x;
        o.y = dy * rs * gm.y + bt.y;
        o.z = dz * rs * gm.z + bt.z;
        o.w = dw * rs * gm.w + bt.w;
        *(float4*)&out[(size_t)gg * DIM + c0] = o;
    }

    // re-zero the edge scratch + counts (safe: all mlp1 reads are done)
    {
        float4 z = make_float4(0.f, 0.f, 0.f, 0.f);
        // NREP*NG*DIM floats = 131072 float4 over 64 blocks = 2048 each
        #pragma unroll
        for (int p = 0; p < 8; p++)
            ((float4*)d_escratch)[bI * 2048 + p * 256 + tid] = z;
        if (tid < 64) d_ecnt[bI * 64 + tid] = 0u;
    }
}

// ---------------------------------------------------------------------------
extern "C" void kernel_launch(void* const* d_in, const int* in_sizes, int n_in,
                              void* d_out, int out_size) {
    const float* x         = (const float*)d_in[0];
    const float* edge_attr = (const float*)d_in[1];
    const float* u         = (const float*)d_in[2];
    const float* W1        = (const float*)d_in[3];
    const float* b1        = (const float*)d_in[4];
    const float* W2        = (const float*)d_in[5];
    const float* b2        = (const float*)d_in[6];
    const float* gamma     = (const float*)d_in[7];
    const float* beta      = (const float*)d_in[8];
    const void* edge_index = d_in[9];
    const void* batch      = d_in[10];

    int n_edges = in_sizes[9] / 2;
    int n_nodes = in_sizes[10];
    float* out = (float*)d_out;

    edgenode_kernel<<<EB + NG, 256>>>(edge_attr, x, edge_index, batch,
                                      n_edges, n_nodes);                   // 1
    mlp1_kernel<<<128, 256>>>(u, W1, b1);                                  // 2
    mlp2_kernel<<<64, 256>>>(u, W2, b2, gamma, beta, out);                 // 3
}

// round 13
// speedup vs baseline: 2.0804x; 1.0916x over previous
#include <cuda_runtime.h>
#include <cstdint>

#define NG    1024
#define DIM   128
#define HID   512
#define NREP  4
#define EB    1184     // edge blocks in fused kernel

// ---- scratch (no allocations allowed) ----
// Zero-initialized at load; mlp2_kernel re-zeroes after the pipeline consumed
// it, so every kernel_launch call observes zeroed scratch (graph-replay safe).
__device__ float    d_escratch[NREP * NG * DIM];   // 2 MB replicated edge sums
__device__ unsigned d_ecnt[NREP * NG];             // replicated edge counts
__device__ float    d_node_mean[NG * DIM];
__device__ float    d_hbuf[NG * HID];              // hidden activations (2 MB)

// ---------------------------------------------------------------------------
__device__ __forceinline__ int load_idx(const void* p, long long i, int idx64) {
    return idx64 ? (int)((const long long*)p)[i] : ((const int*)p)[i];
}
// dtype probe on edge_index: node ids are random nonzero ints, so
// all-zero odd 32-bit words <=> int64 storage.
__device__ __forceinline__ int probe_idx64(const void* edge_index) {
    const int* w = (const int*)edge_index;
    int all_zero = 1;
    #pragma unroll
    for (int i = 1; i < 128; i += 2) all_zero &= (w[i] == 0);
    return all_zero;
}

// red.global.add.v4 WITHOUT a memory clobber: fire-and-forget atomic; register
// deps keep it correct and the compiler can overlap subsequent loads.
__device__ __forceinline__ void red_add_v4(float* dst, float4 v) {
    asm volatile("red.global.add.v4.f32 [%0], {%1,%2,%3,%4};"
                 :: "l"(dst), "f"(v.x), "f"(v.y), "f"(v.z), "f"(v.w));
}

// ---------------------------------------------------------------------------
// K1: blocks 0..EB-1 -> edge scatter (4 edges/iter, parallel index chains)
//     blocks EB..    -> node mean (block per graph, self-computed bounds)
// ---------------------------------------------------------------------------
__global__ void __launch_bounds__(256) edgenode_kernel(
        const float* __restrict__ edge_attr,
        const float* __restrict__ x,
        const void* __restrict__ edge_index,
        const void* __restrict__ batch,
        int n_edges, int n_nodes) {
    int b = blockIdx.x, tid = threadIdx.x;
    int lane = tid & 31;

    if (b < EB) {
        __shared__ int s_idx64;
        if (tid == 0) s_idx64 = probe_idx64(edge_index);
        __syncthreads();
        int idx64 = s_idx64;

        int warp_g = (b * 256 + tid) >> 5;
        int nwarps = (EB * 256) >> 5;
        int stride = nwarps * 4;
        int rep    = warp_g & (NREP - 1);
        const float4* ea = (const float4*)edge_attr;

        // lanes 0..3 each own one index chain per 4-edge batch
        int e = warp_g * 4;
        int gcur = 0;
        if (lane < 4 && e + lane < n_edges) {
            int src = load_idx(edge_index, e + lane, idx64);
            gcur = load_idx(batch, src, idx64);
        }

        for (; e < n_edges; e += stride) {
            // prefetch next batch's graph ids (independent chains)
            int en = e + stride;
            int gnxt = 0;
            if (lane < 4 && en + lane < n_edges) {
                int src = load_idx(edge_index, en + lane, idx64);
                gnxt = load_idx(batch, src, idx64);
            }

            int g0 = __shfl_sync(0xffffffffu, gcur, 0);
            int g1 = __shfl_sync(0xffffffffu, gcur, 1);
            int g2 = __shfl_sync(0xffffffffu, gcur, 2);
            int g3 = __shfl_sync(0xffffffffu, gcur, 3);

            // 4 independent row loads
            float4 v0, v1, v2, v3;
            int h1 = (e + 1 < n_edges), h2 = (e + 2 < n_edges), h3 = (e + 3 < n_edges);
            v0 = ea[(size_t)e * 32 + lane];
            v1 = h1 ? ea[(size_t)(e + 1) * 32 + lane] : make_float4(0, 0, 0, 0);
            v2 = h2 ? ea[(size_t)(e + 2) * 32 + lane] : make_float4(0, 0, 0, 0);
            v3 = h3 ? ea[(size_t)(e + 3) * 32 + lane] : make_float4(0, 0, 0, 0);

            red_add_v4(d_escratch + ((size_t)rep * NG + g0) * DIM + lane * 4, v0);
            if (h1) red_add_v4(d_escratch + ((size_t)rep * NG + g1) * DIM + lane * 4, v1);
            if (h2) red_add_v4(d_escratch + ((size_t)rep * NG + g2) * DIM + lane * 4, v2);
            if (h3) red_add_v4(d_escratch + ((size_t)rep * NG + g3) * DIM + lane * 4, v3);

            // lane-parallel edge counts (lane i holds g_i)
            if (lane < 4 && e + lane < n_edges)
                atomicAdd(&d_ecnt[rep * NG + gcur], 1u);

            gcur = gnxt;
        }
    } else {
        // node mean: graph g's rows are contiguous in x (batch is sorted)
        int g = b - EB;
        __shared__ int s_bound[2];
        if (tid < 2) {
            int idx64 = probe_idx64(edge_index);
            int target = g + tid;
            int lo = 0, hi = n_nodes;
            while (lo < hi) {
                int m = (lo + hi) >> 1;
                if (load_idx(batch, m, idx64) < target) lo = m + 1; else hi = m;
            }
            s_bound[tid] = lo;
        }
        __syncthreads();
        int s = s_bound[0], e = s_bound[1];
        int cnt = e - s;
        int w = tid >> 5;

        const float4* xr = (const float4*)x;
        float4 acc = make_float4(0.f, 0.f, 0.f, 0.f);
        for (int n = s + w; n < e; n += 8) {
            float4 v = xr[(size_t)n * 32 + lane];
            acc.x += v.x; acc.y += v.y; acc.z += v.z; acc.w += v.w;
        }
        __shared__ float4 s_red[8][32];
        s_red[w][lane] = acc;
        __syncthreads();
        if (w == 0) {
            float4 t = s_red[0][lane];
            #pragma unroll
            for (int i = 1; i < 8; i++) {
                float4 q = s_red[i][lane];
                t.x += q.x; t.y += q.y; t.z += q.z; t.w += q.w;
            }
            float inv = 1.0f / (float)(cnt > 0 ? cnt : 1);
            t.x *= inv; t.y *= inv; t.z *= inv; t.w *= inv;
            ((float4*)(d_node_mean + (size_t)g * DIM))[lane] = t;
        }
    }
}

// ---------------------------------------------------------------------------
// K2 (mlp1): h = relu(inp @ W1 + b1), W1 staged in smem.
// 256 blocks = 16 col-slices (32 cols) x 16 graph-tiles (64 graphs).
// 256 threads: tx = tid&7 -> 4 cols, ty = tid>>3 -> 2 graphs. 6 k-chunks of 64.
// ---------------------------------------------------------------------------
__global__ void __launch_bounds__(256) mlp1_kernel(
        const float* __restrict__ u,
        const float* __restrict__ W1, const float* __restrict__ b1) {
    __shared__ float w1c[64 * 32];        // 8 KB: W1 chunk [64 k][32 cols]
    __shared__ float inps[64 * 65];       // 16.6 KB: inp [64 g][64 k + pad]
    __shared__ float s_inv[64];           // 1/edge_count per graph

    int bI = blockIdx.x;
    int sl = bI & 15;          // col slice (32 cols)
    int tI = bI >> 4;          // graph tile (64 graphs)
    int gbase = tI * 64;
    int tid = threadIdx.x;
    int tx = tid & 7, ty = tid >> 3;

    if (tid < 64) {
        unsigned c = 0;
        #pragma unroll
        for (int r = 0; r < NREP; r++) c += d_ecnt[r * NG + gbase + tid];
        s_inv[tid] = 1.0f / (float)(c > 0u ? c : 1u);
    }

    float4 bb = *(const float4*)&b1[sl * 32 + tx * 4];
    float acc[2][4];
    #pragma unroll
    for (int gi = 0; gi < 2; gi++) {
        acc[gi][0] = bb.x; acc[gi][1] = bb.y; acc[gi][2] = bb.z; acc[gi][3] = bb.w;
    }

    for (int ch = 0; ch < 6; ch++) {
        int kc = ch * 64;
        __syncthreads();   // protect smem from previous chunk's readers

        // stage W1 chunk [64 rows][32 cols]: 512 float4, 2 per thread
        #pragma unroll
        for (int p = 0; p < 2; p++) {
            int idx = tid + p * 256;
            int row = idx >> 3, cc = idx & 7;
            *(float4*)&w1c[row * 32 + cc * 4] =
                *(const float4*)&W1[(size_t)(kc + row) * HID + sl * 32 + cc * 4];
        }
        // stage inp chunk [64 graphs][64 features]: 1024 float4
        #pragma unroll
        for (int p = 0; p < 4; p++) {
            int idx = tid + p * 256;
            int g = idx >> 4, kq = idx & 15;
            int gg = gbase + g;
            float4 v;
            if (ch < 2) {
                v = *(const float4*)&u[(size_t)gg * DIM + kc + kq * 4];
            } else if (ch < 4) {
                int col = kc - 128 + kq * 4;
                v = make_float4(0.f, 0.f, 0.f, 0.f);
                #pragma unroll
                for (int r = 0; r < NREP; r++) {
                    float4 q = *(const float4*)&d_escratch[((size_t)r * NG + gg) * DIM + col];
                    v.x += q.x; v.y += q.y; v.z += q.z; v.w += q.w;
                }
                float iv = s_inv[g];
                v.x *= iv; v.y *= iv; v.z *= iv; v.w *= iv;
            } else {
                v = *(const float4*)&d_node_mean[(size_t)gg * DIM + kc - 256 + kq * 4];
            }
            float* dst = &inps[g * 65 + kq * 4];
            dst[0] = v.x; dst[1] = v.y; dst[2] = v.z; dst[3] = v.w;
        }
        __syncthreads();

        #pragma unroll 4
        for (int kk = 0; kk < 64; kk++) {
            float4 wv = *(const float4*)&w1c[kk * 32 + tx * 4];
            float x0 = inps[(ty * 2 + 0) * 65 + kk];
            float x1 = inps[(ty * 2 + 1) * 65 + kk];
            acc[0][0] = fmaf(x0, wv.x, acc[0][0]); acc[0][1] = fmaf(x0, wv.y, acc[0][1]);
            acc[0][2] = fmaf(x0, wv.z, acc[0][2]); acc[0][3] = fmaf(x0, wv.w, acc[0][3]);
            acc[1][0] = fmaf(x1, wv.x, acc[1][0]); acc[1][1] = fmaf(x1, wv.y, acc[1][1]);
            acc[1][2] = fmaf(x1, wv.z, acc[1][2]); acc[1][3] = fmaf(x1, wv.w, acc[1][3]);
        }
    }

    // write h with relu (float4)
    #pragma unroll
    for (int gi = 0; gi < 2; gi++) {
        int gg = gbase + ty * 2 + gi;
        float4 o;
        o.x = fmaxf(acc[gi][0], 0.f); o.y = fmaxf(acc[gi][1], 0.f);
        o.z = fmaxf(acc[gi][2], 0.f); o.w = fmaxf(acc[gi][3], 0.f);
        *(float4*)&d_hbuf[(size_t)gg * HID + sl * 32 + tx * 4] = o;
    }
}

// ---------------------------------------------------------------------------
// K3 (mlp2): y = LayerNorm(h @ W2 + b2 + u), W2 staged in smem.
// 128 blocks x 8 graphs, 256 threads; warp w owns graph w, lane owns 4 cols.
// 8 k-chunks of 64. Also re-zeroes scratch.
// ---------------------------------------------------------------------------
__global__ void __launch_bounds__(256) mlp2_kernel(
        const float* __restrict__ u,
        const float* __restrict__ W2, const float* __restrict__ b2,
        const float* __restrict__ gamma, const float* __restrict__ beta,
        float* __restrict__ out) {
    __shared__ float w2c[64 * 128];    // 32 KB: W2 chunk [64 k][128 cols]
    __shared__ float hs[8 * 64];       // 2 KB: h chunk [8 g][64 k]

    int bI = blockIdx.x;
    int gbase = bI * 8;
    int tid = threadIdx.x;
    int w = tid >> 5, lane = tid & 31;
    int c0 = lane * 4;

    float4 a = *(const float4*)&b2[c0];

    for (int ch = 0; ch < 8; ch++) {
        int kc = ch * 64;
        __syncthreads();
        // stage W2 chunk: 2048 float4, 8 per thread
        #pragma unroll
        for (int p = 0; p < 8; p++) {
            int idx = tid + p * 256;
            int row = idx >> 5, cg = idx & 31;
            *(float4*)&w2c[row * 128 + cg * 4] =
                *(const float4*)&W2[(size_t)(kc + row) * DIM + cg * 4];
        }
        // stage h chunk: 8 g x 16 float4 = 128 threads
        if (tid < 128) {
            int g = tid >> 4, kq = tid & 15;
            *(float4*)&hs[g * 64 + kq * 4] =
                *(const float4*)&d_hbuf[(size_t)(gbase + g) * HID + kc + kq * 4];
        }
        __syncthreads();

        #pragma unroll 4
        for (int kk = 0; kk < 64; kk++) {
            float hv = hs[w * 64 + kk];
            float4 wv = *(const float4*)&w2c[kk * 128 + c0];
            a.x = fmaf(hv, wv.x, a.x); a.y = fmaf(hv, wv.y, a.y);
            a.z = fmaf(hv, wv.z, a.z); a.w = fmaf(hv, wv.w, a.w);
        }
    }

    // residual + layernorm (warp w -> graph gbase+w)
    {
        int gg = gbase + w;
        float4 uu = *(const float4*)&u[(size_t)gg * DIM + c0];
        a.x += uu.x; a.y += uu.y; a.z += uu.z; a.w += uu.w;

        float sm = a.x + a.y + a.z + a.w;
        #pragma unroll
        for (int off = 16; off; off >>= 1) sm += __shfl_xor_sync(0xffffffffu, sm, off);
        float mu = sm * (1.0f / DIM);

        float dx = a.x - mu, dy = a.y - mu, dz = a.z - mu, dw = a.w - mu;
        float sq = dx * dx + dy * dy + dz * dz + dw * dw;
        #pragma unroll
        for (int off = 16; off; off >>= 1) sq += __shfl_xor_sync(0xffffffffu, sq, off);
        float rs = rsqrtf(sq * (1.0f / DIM) + 1e-5f);

        float4 gm = *(const float4*)&gamma[c0];
        float4 bt = *(const float4*)&beta[c0];
        float4 o;
        o.x = dx * rs * gm.x + bt.x;
        o.y = dy * rs * gm.y + bt.y;
        o.z = dz * rs * gm.z + bt.z;
        o.w = dw * rs * gm.w + bt.w;
        *(float4*)&out[(size_t)gg * DIM + c0] = o;
    }

    // re-zero the edge scratch + counts (safe: all mlp1 reads are done)
    {
        float4 z = make_float4(0.f, 0.f, 0.f, 0.f);
        // NREP*NG*DIM floats = 131072 float4 over 128 blocks = 1024 each
        #pragma unroll
        for (int p = 0; p < 4; p++)
            ((float4*)d_escratch)[bI * 1024 + p * 256 + tid] = z;
        if (tid < 32) d_ecnt[bI * 32 + tid] = 0u;
    }
}

// ---------------------------------------------------------------------------
extern "C" void kernel_launch(void* const* d_in, const int* in_sizes, int n_in,
                              void* d_out, int out_size) {
    const float* x         = (const float*)d_in[0];
    const float* edge_attr = (const float*)d_in[1];
    const float* u         = (const float*)d_in[2];
    const float* W1        = (const float*)d_in[3];
    const float* b1        = (const float*)d_in[4];
    const float* W2        = (const float*)d_in[5];
    const float* b2        = (const float*)d_in[6];
    const float* gamma     = (const float*)d_in[7];
    const float* beta      = (const float*)d_in[8];
    const void* edge_index = d_in[9];
    const void* batch      = d_in[10];

    int n_edges = in_sizes[9] / 2;
    int n_nodes = in_sizes[10];
    float* out = (float*)d_out;

    edgenode_kernel<<<EB + NG, 256>>>(edge_attr, x, edge_index, batch,
                                      n_edges, n_nodes);                   // 1
    mlp1_kernel<<<256, 256>>>(u, W1, b1);                                  // 2
    mlp2_kernel<<<128, 256>>>(u, W2, b2, gamma, beta, out);                // 3
}